// round 4
// baseline (speedup 1.0000x reference)
#include <cuda_runtime.h>
#include <cuda_bf16.h>
#include <math.h>

// Problem constants
#define Hd 1024
#define Ld 4
#define DI 2048
#define Nst 16
#define Kc 4
#define BATCH 2
#define SEQ 1024
#define TOK (BATCH*SEQ)          // 2048 tokens

// ---------------- scratch buffers (device globals; no allocation) -------------
__device__ float g_x  [TOK*Hd];      // running hidden (H)
__device__ float g_xn [TOK*Hd];      // layernormed hidden
__device__ float g_xr [TOK*2*DI];    // in_proj output (x_inner_raw | res)
__device__ float g_c1 [TOK*DI];      // conv1 output
__device__ float g_xi [TOK*DI];      // final x_inner (post conv2+silu)
__device__ float g_proj[TOK*33];     // x_proj output (dt | B | C)
__device__ float g_y  [TOK*DI];      // scan output + x_inner*D
__device__ float g_y2 [TOK*DI];      // after mamba_ln * sigmoid(res)
__device__ float g_t1 [TOK*Hd];      // MLP intermediate

// ---------------- helpers ----------------------------------------------------
__device__ __forceinline__ float sigmoidf_(float x){ return 1.f/(1.f+__expf(-x)); }
__device__ __forceinline__ float siluf_(float x){ return x * (1.f/(1.f+__expf(-x))); }
__device__ __forceinline__ float geluf_(float x){ return 0.5f*x*(1.f+erff(x*0.70710678118654752f)); }

__device__ __forceinline__ float block_reduce_sum(float v, float* red){
    int tid = threadIdx.x;
    #pragma unroll
    for (int o=16;o;o>>=1) v += __shfl_xor_sync(0xffffffffu, v, o);
    if ((tid&31)==0) red[tid>>5] = v;
    __syncthreads();
    if (tid==0){
        float s = 0.f;
        #pragma unroll
        for (int i=0;i<8;i++) s += red[i];
        red[0] = s;
    }
    __syncthreads();
    float r = red[0];
    __syncthreads();
    return r;
}

// ---------------- layernorm (optionally fused * sigmoid(res)) ----------------
// MODE 0: out = ln(x)*g+b          MODE 1: out = (ln(x)*g+b) * sigmoid(res[...])
template<int COLS, int MODE>
__global__ void __launch_bounds__(256) layernorm_k(
    const float* __restrict__ in, const float* __restrict__ gg,
    const float* __restrict__ bb, float* __restrict__ out,
    const float* __restrict__ res, int resLd, int resOff)
{
    constexpr int VPT = COLS/256;
    __shared__ float red[8];
    int row = blockIdx.x;
    const float* x = in + (size_t)row*COLS;
    float v[VPT];
    float s = 0.f;
    #pragma unroll
    for (int i=0;i<VPT;i++){ v[i] = x[i*256 + threadIdx.x]; s += v[i]; }
    s = block_reduce_sum(s, red);
    float mu = s * (1.f/COLS);
    float q = 0.f;
    #pragma unroll
    for (int i=0;i<VPT;i++){ float c = v[i]-mu; q += c*c; }
    q = block_reduce_sum(q, red);
    float rstd = rsqrtf(q*(1.f/COLS) + 1e-5f);
    #pragma unroll
    for (int i=0;i<VPT;i++){
        int c = i*256 + threadIdx.x;
        float o = (v[i]-mu)*rstd*gg[c] + bb[c];
        if (MODE==1){
            float r = res[(size_t)row*resLd + resOff + c];
            o *= sigmoidf_(r);
        }
        out[(size_t)row*COLS + c] = o;
    }
}

// ---------------- SGEMM NT: C[m,n] = sum_k A[m,k]*B[n,k]  (+ epilogue) --------
// A: M x K row-major, B: N x K row-major. M,N multiples of 128, K multiple of 8.
#define BM 128
#define BN 128
#define BKK 8
// EPI: 0 none | 1 gelu(acc+bias) | 2 acc+R1 | 3 acc+bias+R1
template<int EPI>
__global__ void __launch_bounds__(256) sgemm_nt(
    const float* __restrict__ A, const float* __restrict__ B, float* __restrict__ C,
    int M, int N, int K,
    const float* __restrict__ bias, const float* __restrict__ R1)
{
    __shared__ float As[2][BKK][BM];
    __shared__ float Bs[2][BKK][BN];
    int tid = threadIdx.x;
    int bm = blockIdx.y * BM;
    int bn = blockIdx.x * BN;

    int lrow = tid >> 1;           // 0..127
    int lk   = (tid & 1) * 4;      // 0 or 4
    const float* Aptr = A + (size_t)(bm + lrow)*K + lk;
    const float* Bptr = B + (size_t)(bn + lrow)*K + lk;

    int tx = tid & 15, ty = tid >> 4;
    float acc[8][8];
    #pragma unroll
    for (int i=0;i<8;i++)
        #pragma unroll
        for (int j=0;j<8;j++) acc[i][j] = 0.f;

    // prologue: tile 0
    float4 av = *(const float4*)Aptr;
    float4 bv = *(const float4*)Bptr;
    As[0][lk+0][lrow]=av.x; As[0][lk+1][lrow]=av.y; As[0][lk+2][lrow]=av.z; As[0][lk+3][lrow]=av.w;
    Bs[0][lk+0][lrow]=bv.x; Bs[0][lk+1][lrow]=bv.y; Bs[0][lk+2][lrow]=bv.z; Bs[0][lk+3][lrow]=bv.w;
    __syncthreads();

    int nk = K / BKK;
    for (int kt = 0; kt < nk; kt++){
        int cur = kt & 1, nxt = cur ^ 1;
        if (kt+1 < nk){
            av = *(const float4*)(Aptr + (size_t)(kt+1)*BKK);
            bv = *(const float4*)(Bptr + (size_t)(kt+1)*BKK);
        }
        #pragma unroll
        for (int k=0;k<BKK;k++){
            float4 a0 = *(const float4*)&As[cur][k][ty*8];
            float4 a1 = *(const float4*)&As[cur][k][ty*8+4];
            float4 b0 = *(const float4*)&Bs[cur][k][tx*8];
            float4 b1 = *(const float4*)&Bs[cur][k][tx*8+4];
            float af[8] = {a0.x,a0.y,a0.z,a0.w,a1.x,a1.y,a1.z,a1.w};
            float bf[8] = {b0.x,b0.y,b0.z,b0.w,b1.x,b1.y,b1.z,b1.w};
            #pragma unroll
            for (int i=0;i<8;i++)
                #pragma unroll
                for (int j=0;j<8;j++)
                    acc[i][j] = fmaf(af[i], bf[j], acc[i][j]);
        }
        if (kt+1 < nk){
            As[nxt][lk+0][lrow]=av.x; As[nxt][lk+1][lrow]=av.y; As[nxt][lk+2][lrow]=av.z; As[nxt][lk+3][lrow]=av.w;
            Bs[nxt][lk+0][lrow]=bv.x; Bs[nxt][lk+1][lrow]=bv.y; Bs[nxt][lk+2][lrow]=bv.z; Bs[nxt][lk+3][lrow]=bv.w;
        }
        __syncthreads();
    }

    // epilogue
    #pragma unroll
    for (int i=0;i<8;i++){
        int m = bm + ty*8 + i;
        #pragma unroll
        for (int j0=0;j0<8;j0+=4){
            int n = bn + tx*8 + j0;
            size_t idx = (size_t)m*N + n;
            float4 o;
            float vv[4];
            #pragma unroll
            for (int j=0;j<4;j++){
                float a = acc[i][j0+j];
                if (EPI==1)      a = geluf_(a + bias[n+j]);
                else if (EPI==2) a = a + R1[idx+j];
                else if (EPI==3) a = a + bias[n+j] + R1[idx+j];
                vv[j]=a;
            }
            o.x=vv[0]; o.y=vv[1]; o.z=vv[2]; o.w=vv[3];
            *(float4*)&C[idx] = o;
        }
    }
}

// ---------------- depthwise causal conv (K=4) + silu --------------------------
// out[(b*S+s)*DI+d] = silu( bias[d] + sum_k act(in[(b*S+s-3+k)*ld + d]) * w[d*4+k] )
template<bool IN_SILU>
__global__ void __launch_bounds__(256) dwconv_silu_k(
    const float* __restrict__ in, int ld,
    const float* __restrict__ w, const float* __restrict__ bias,
    float* __restrict__ out)
{
    int idx = blockIdx.x*256 + threadIdx.x;
    if (idx >= BATCH*SEQ*DI) return;
    int d = idx & (DI-1);
    int s = (idx >> 11) & (SEQ-1);
    int b = idx >> 21;
    const float* base = in + (size_t)b*SEQ*ld + d;
    float acc = bias[d];
    #pragma unroll
    for (int k=0;k<Kc;k++){
        int t = s - (Kc-1) + k;
        if (t >= 0){
            float xv = base[(size_t)t*ld];
            if (IN_SILU) xv = siluf_(xv);
            acc = fmaf(xv, w[d*Kc+k], acc);
        }
    }
    out[idx] = siluf_(acc);
}

// ---------------- x_proj: proj[t, j] = sum_k xi[t,k] * W[j,k]  (J=33) ---------
__global__ void __launch_bounds__(256) xproj_k(
    const float* __restrict__ xi, const float* __restrict__ W,
    float* __restrict__ proj)
{
    __shared__ float sA[DI];
    int tok = blockIdx.x;
    const float* a = xi + (size_t)tok*DI;
    for (int i=threadIdx.x; i<DI; i+=256) sA[i] = a[i];
    __syncthreads();
    int w = threadIdx.x >> 5, lane = threadIdx.x & 31;
    for (int j = w; j < 33; j += 8){
        const float* Bw = W + (size_t)j*DI;
        float s = 0.f;
        for (int k = lane; k < DI; k += 32) s = fmaf(sA[k], Bw[k], s);
        #pragma unroll
        for (int o=16;o;o>>=1) s += __shfl_xor_sync(0xffffffffu, s, o);
        if (lane==0) proj[(size_t)tok*33 + j] = s;
    }
}

// ---------------- selective scan ---------------------------------------------
// One thread per (batch, channel). 16 states in registers. proj staged in SMEM.
#define TCH 64
__global__ void __launch_bounds__(128) scan_k(
    const float* __restrict__ proj, const float* __restrict__ xi,
    const float* __restrict__ dtw, const float* __restrict__ dtb,
    const float* __restrict__ Dp, float* __restrict__ y)
{
    int b = blockIdx.y;
    int d = blockIdx.x*128 + threadIdx.x;
    float w_dt = dtw[d];
    float b_dt = dtb[d];
    float Dd   = Dp[d];
    float h[Nst];
    #pragma unroll
    for (int n=0;n<Nst;n++) h[n]=0.f;

    // layout: slot 0 = dt_raw, slots 4..19 = B, slots 20..35 = C  (16B aligned)
    __shared__ float sp[TCH][36];
    const float* projB = proj + (size_t)b*SEQ*33;
    const float* xiB   = xi   + (size_t)b*SEQ*DI + d;
    float*       yB    = y    + (size_t)b*SEQ*DI + d;

    for (int t0=0; t0<SEQ; t0+=TCH){
        __syncthreads();
        for (int i=threadIdx.x; i<TCH*33; i+=128){
            int t = i/33, j = i%33;
            int slot = (j==0) ? 0 : (j+3);
            sp[t][slot] = projB[(size_t)(t0)*33 + i];
        }
        __syncthreads();
        for (int tt=0; tt<TCH; tt++){
            int t = t0+tt;
            const float* r = sp[tt];
            float z = fmaf(r[0], w_dt, b_dt);
            float dt = (z > 15.f) ? z : log1pf(__expf(z));
            float xv = xiB[(size_t)t*DI];
            float4 B0 = *(const float4*)&r[4];
            float4 B1 = *(const float4*)&r[8];
            float4 B2 = *(const float4*)&r[12];
            float4 B3 = *(const float4*)&r[16];
            float4 C0 = *(const float4*)&r[20];
            float4 C1 = *(const float4*)&r[24];
            float4 C2 = *(const float4*)&r[28];
            float4 C3 = *(const float4*)&r[32];
            float bArr[16] = {B0.x,B0.y,B0.z,B0.w,B1.x,B1.y,B1.z,B1.w,
                              B2.x,B2.y,B2.z,B2.w,B3.x,B3.y,B3.z,B3.w};
            float cArr[16] = {C0.x,C0.y,C0.z,C0.w,C1.x,C1.y,C1.z,C1.w,
                              C2.x,C2.y,C2.z,C2.w,C3.x,C3.y,C3.z,C3.w};
            float yv = 0.f;
            #pragma unroll
            for (int n=0;n<Nst;n++){
                float An = -(float)(n+1);
                float u = fmaf(h[n], An, xv * bArr[n]);
                h[n] = fmaf(dt, u, h[n]);
                yv = fmaf(h[n], cArr[n], yv);
            }
            yB[(size_t)t*DI] = fmaf(xv, Dd, yv);
        }
    }
}

// ---------------- host side ---------------------------------------------------
static float* sym_addr(const void* symbol){
    void* p = nullptr;
    cudaGetSymbolAddress(&p, symbol);
    return (float*)p;
}

extern "C" void kernel_launch(void* const* d_in, const int* in_sizes, int n_in,
                              void* d_out, int out_size)
{
    const float* hidden   = (const float*)d_in[0];
    const float* in_ng    = (const float*)d_in[1];
    const float* in_nb    = (const float*)d_in[2];
    const float* ln_g     = (const float*)d_in[3];
    const float* ln_b     = (const float*)d_in[4];
    const float* in_proj  = (const float*)d_in[5];   // (L, 2*DI, H)
    const float* conv_w   = (const float*)d_in[6];   // (L, 2, DI, K)
    const float* conv_b   = (const float*)d_in[7];   // (L, 2, DI)
    const float* x_proj   = (const float*)d_in[8];   // (L, 33, DI)
    const float* dt_w     = (const float*)d_in[9];   // (L, DI, 1)
    const float* dt_b     = (const float*)d_in[10];  // (L, DI)
    const float* Dparam   = (const float*)d_in[11];  // (L, DI)
    const float* mln_g    = (const float*)d_in[12];
    const float* mln_b    = (const float*)d_in[13];
    const float* out_proj = (const float*)d_in[14];  // (L, H, DI)
    const float* op1_w    = (const float*)d_in[15];
    const float* op1_b    = (const float*)d_in[16];
    const float* op2_w    = (const float*)d_in[17];
    const float* op2_b    = (const float*)d_in[18];
    float* out = (float*)d_out;

    float* x   = sym_addr(g_x);
    float* xn  = sym_addr(g_xn);
    float* xr  = sym_addr(g_xr);
    float* c1  = sym_addr(g_c1);
    float* xi  = sym_addr(g_xi);
    float* pj  = sym_addr(g_proj);
    float* yb  = sym_addr(g_y);
    float* y2  = sym_addr(g_y2);
    float* t1  = sym_addr(g_t1);

    // x = LN(hidden)
    layernorm_k<Hd,0><<<TOK,256>>>(hidden, in_ng, in_nb, x, nullptr, 0, 0);

    for (int l=0; l<Ld; l++){
        // xn = LN_l(x)
        layernorm_k<Hd,0><<<TOK,256>>>(x, ln_g + l*Hd, ln_b + l*Hd, xn, nullptr, 0, 0);
        // xr = xn @ in_proj_w[l]^T   (TOK x 4096)
        {
            dim3 grid(2*DI/BN, TOK/BM);
            sgemm_nt<0><<<grid,256>>>(xn, in_proj + (size_t)l*2*DI*Hd, xr,
                                      TOK, 2*DI, Hd, nullptr, nullptr);
        }
        // conv1: input = silu(xr[:, :DI]) (ld 4096), output silu -> c1
        {
            int total = BATCH*SEQ*DI;
            dwconv_silu_k<true><<<(total+255)/256,256>>>(
                xr, 2*DI,
                conv_w + (size_t)(l*2+0)*DI*Kc, conv_b + (size_t)(l*2+0)*DI, c1);
            // conv2: input = c1 (ld 2048), output silu -> xi
            dwconv_silu_k<false><<<(total+255)/256,256>>>(
                c1, DI,
                conv_w + (size_t)(l*2+1)*DI*Kc, conv_b + (size_t)(l*2+1)*DI, xi);
        }
        // proj = xi @ x_proj_w[l]^T  (TOK x 33)
        xproj_k<<<TOK,256>>>(xi, x_proj + (size_t)l*33*DI, pj);
        // scan -> y (+ xi * D fused)
        {
            dim3 grid(DI/128, BATCH);
            scan_k<<<grid,128>>>(pj, xi, dt_w + (size_t)l*DI, dt_b + (size_t)l*DI,
                                 Dparam + (size_t)l*DI, yb);
        }
        // y2 = LN_mamba(y) * sigmoid(res)   (res = xr[:, DI:])
        layernorm_k<DI,1><<<TOK,256>>>(yb, mln_g + (size_t)l*DI, mln_b + (size_t)l*DI,
                                       y2, xr, 2*DI, DI);
        // x = x + y2 @ out_proj_w[l]^T
        {
            dim3 grid(Hd/BN, TOK/BM);
            sgemm_nt<2><<<grid,256>>>(y2, out_proj + (size_t)l*Hd*DI, x,
                                      TOK, Hd, DI, nullptr, x);
        }
    }

    // MLP: t1 = gelu(x @ op1^T + b1)
    {
        dim3 grid(Hd/BN, TOK/BM);
        sgemm_nt<1><<<grid,256>>>(x, op1_w, t1, TOK, Hd, Hd, op1_b, nullptr);
        // out = t1 @ op2^T + b2 + hidden   (NOTE: reference does NOT add x here)
        sgemm_nt<3><<<grid,256>>>(t1, op2_w, out, TOK, Hd, Hd, op2_b, hidden);
    }
}

// round 11
// speedup vs baseline: 1.4929x; 1.4929x over previous
#include <cuda_runtime.h>
#include <cuda_bf16.h>
#include <math.h>
#include <stdint.h>

// Problem constants
#define Hd 1024
#define Ld 4
#define DI 2048
#define Nst 16
#define Kc 4
#define BATCH 2
#define SEQ 1024
#define TOK (BATCH*SEQ)          // 2048 tokens

// ---------------- scratch buffers (device globals; no allocation) -------------
__device__ float g_x  [TOK*Hd];
__device__ float g_xn [TOK*Hd];
__device__ float g_xr [TOK*2*DI];
__device__ float g_c1 [TOK*DI];
__device__ float g_xi [TOK*DI];
__device__ float g_proj[TOK*33];
__device__ float g_y  [TOK*DI];
__device__ float g_y2 [TOK*DI];
__device__ float g_t1 [TOK*Hd];

// ---------------- helpers ----------------------------------------------------
__device__ __forceinline__ float sigmoidf_(float x){ return 1.f/(1.f+__expf(-x)); }
__device__ __forceinline__ float siluf_(float x){ return x * (1.f/(1.f+__expf(-x))); }
__device__ __forceinline__ float geluf_(float x){ return 0.5f*x*(1.f+erff(x*0.70710678118654752f)); }

__device__ __forceinline__ uint32_t smem_u32(const void* p){
    uint32_t a;
    asm("{ .reg .u64 t; cvta.to.shared.u64 t, %1; cvt.u32.u64 %0, t; }" : "=r"(a) : "l"(p));
    return a;
}

__device__ __forceinline__ void ldsm_x4(uint32_t* r, uint32_t addr){
    asm volatile("ldmatrix.sync.aligned.m8n8.x4.shared.b16 {%0,%1,%2,%3}, [%4];"
        : "=r"(r[0]), "=r"(r[1]), "=r"(r[2]), "=r"(r[3]) : "r"(addr));
}
__device__ __forceinline__ void ldsm_x2(uint32_t* r, uint32_t addr){
    asm volatile("ldmatrix.sync.aligned.m8n8.x2.shared.b16 {%0,%1}, [%2];"
        : "=r"(r[0]), "=r"(r[1]) : "r"(addr));
}
__device__ __forceinline__ void mma_bf16(float* c, const uint32_t* a, const uint32_t* b){
    asm volatile(
        "mma.sync.aligned.m16n8k16.row.col.f32.bf16.bf16.f32 "
        "{%0,%1,%2,%3}, {%4,%5,%6,%7}, {%8,%9}, {%0,%1,%2,%3};"
        : "+f"(c[0]), "+f"(c[1]), "+f"(c[2]), "+f"(c[3])
        : "r"(a[0]), "r"(a[1]), "r"(a[2]), "r"(a[3]), "r"(b[0]), "r"(b[1]));
}

// ---------------- tensor-core GEMM NT with bf16 hi/lo split -------------------
// C[m,n] = sum_k A[m,k]*B[n,k];  A: MxK, B: NxK row-major fp32.
// M,N multiples of 128, K multiple of 32.
#define BM 128
#define BN 128
#define BKf 32              // fp32 K per chunk
#define PITCH 40            // bf16 elems per smem row (80 B, conflict-free ldmatrix)
#define TILE_B (128*PITCH*2)          // 10240 B per matrix tile
#define ST_AHI 0
#define ST_ALO (1*TILE_B)
#define ST_BHI (2*TILE_B)
#define ST_BLO (3*TILE_B)
#define STAGE_B (4*TILE_B)            // 40960 B per stage
#define GEMM_SMEM (2*STAGE_B)         // 81920 B

// EPI: 0 none | 1 gelu(acc+bias) | 2 acc+R1 | 3 acc+bias+R1
template<int EPI>
__global__ void __launch_bounds__(256, 1) mma_gemm_nt(
    const float* __restrict__ A, const float* __restrict__ B, float* __restrict__ C,
    int M, int N, int K,
    const float* __restrict__ bias, const float* __restrict__ R1)
{
    extern __shared__ char smem[];
    const uint32_t smb = smem_u32(smem);
    const int tid  = threadIdx.x;
    const int wid  = tid >> 5;
    const int lane = tid & 31;
    const int bm = blockIdx.y * BM;
    const int bn = blockIdx.x * BN;
    const int warp_m = (wid >> 2) * 64;     // 0 or 64
    const int warp_n = (wid & 3) * 32;      // 0,32,64,96

    // global load mapping: row = tid/2 (0..127), colb = (tid&1)*16
    const int grow = tid >> 1;
    const int gcol = (tid & 1) * 16;
    const float* Ag = A + (size_t)(bm + grow)*K + gcol;
    const float* Bg = B + (size_t)(bn + grow)*K + gcol;
    const uint32_t st_off = (uint32_t)grow*(PITCH*2) + (uint32_t)gcol*2; // byte off in tile

    // ldmatrix lane address components (byte offsets within a tile)
    const int a_r  = ((lane >> 3) & 1)*8 + (lane & 7);     // m row within 16
    const int a_k8 = (lane >> 4) * 8;                      // k half
    const uint32_t a_lane_off = (uint32_t)(warp_m + a_r)*(PITCH*2) + (uint32_t)a_k8*2;
    const int l16  = lane & 15;
    const int b_r  = l16 & 7;
    const int b_h  = (l16 >> 3);
    const uint32_t b_lane_off = (uint32_t)(warp_n + b_r)*(PITCH*2) + (uint32_t)b_h*16;

    float acc[4][4][4];
    #pragma unroll
    for (int i=0;i<4;i++)
        #pragma unroll
        for (int j=0;j<4;j++)
            #pragma unroll
            for (int q=0;q<4;q++) acc[i][j][q]=0.f;

    const int NK = K / BKf;
    float4 aR[4], bR[4];

    // ---- load chunk into regs ----
    auto load_regs = [&](int kc){
        const float* ap = Ag + kc*BKf;
        const float* bp = Bg + kc*BKf;
        #pragma unroll
        for (int q=0;q<4;q++){ aR[q] = *(const float4*)(ap + q*4); bR[q] = *(const float4*)(bp + q*4); }
    };
    // ---- convert regs -> smem stage ----
    auto store_stage = [&](int s){
        uint32_t base = smb + s*STAGE_B;
        #pragma unroll
        for (int q=0;q<4;q++){
            float4 v = aR[q];
            __nv_bfloat16 h0=__float2bfloat16(v.x), h1=__float2bfloat16(v.y),
                          h2=__float2bfloat16(v.z), h3=__float2bfloat16(v.w);
            __nv_bfloat162 hp0; hp0.x=h0; hp0.y=h1;
            __nv_bfloat162 hp1; hp1.x=h2; hp1.y=h3;
            __nv_bfloat162 lp0; lp0.x=__float2bfloat16(v.x-__bfloat162float(h0));
                                lp0.y=__float2bfloat16(v.y-__bfloat162float(h1));
            __nv_bfloat162 lp1; lp1.x=__float2bfloat16(v.z-__bfloat162float(h2));
                                lp1.y=__float2bfloat16(v.w-__bfloat162float(h3));
            uint32_t o = st_off + q*8;
            asm volatile("st.shared.v2.b32 [%0], {%1,%2};" ::
                "r"(base + ST_AHI + o), "r"(*(uint32_t*)&hp0), "r"(*(uint32_t*)&hp1) : "memory");
            asm volatile("st.shared.v2.b32 [%0], {%1,%2};" ::
                "r"(base + ST_ALO + o), "r"(*(uint32_t*)&lp0), "r"(*(uint32_t*)&lp1) : "memory");
        }
        #pragma unroll
        for (int q=0;q<4;q++){
            float4 v = bR[q];
            __nv_bfloat16 h0=__float2bfloat16(v.x), h1=__float2bfloat16(v.y),
                          h2=__float2bfloat16(v.z), h3=__float2bfloat16(v.w);
            __nv_bfloat162 hp0; hp0.x=h0; hp0.y=h1;
            __nv_bfloat162 hp1; hp1.x=h2; hp1.y=h3;
            __nv_bfloat162 lp0; lp0.x=__float2bfloat16(v.x-__bfloat162float(h0));
                                lp0.y=__float2bfloat16(v.y-__bfloat162float(h1));
            __nv_bfloat162 lp1; lp1.x=__float2bfloat16(v.z-__bfloat162float(h2));
                                lp1.y=__float2bfloat16(v.w-__bfloat162float(h3));
            uint32_t o = st_off + q*8;
            asm volatile("st.shared.v2.b32 [%0], {%1,%2};" ::
                "r"(base + ST_BHI + o), "r"(*(uint32_t*)&hp0), "r"(*(uint32_t*)&hp1) : "memory");
            asm volatile("st.shared.v2.b32 [%0], {%1,%2};" ::
                "r"(base + ST_BLO + o), "r"(*(uint32_t*)&lp0), "r"(*(uint32_t*)&lp1) : "memory");
        }
    };
    // ---- compute one chunk from smem stage ----
    auto compute_stage = [&](int s){
        uint32_t base = smb + s*STAGE_B;
        #pragma unroll
        for (int kk=0; kk<BKf; kk+=16){
            uint32_t ahi[4][4], alo[4][4], bhi[4][2], blo[4][2];
            #pragma unroll
            for (int tm=0; tm<4; tm++){
                uint32_t o = a_lane_off + (uint32_t)tm*16*(PITCH*2) + (uint32_t)kk*2;
                ldsm_x4(ahi[tm], base + ST_AHI + o);
                ldsm_x4(alo[tm], base + ST_ALO + o);
            }
            #pragma unroll
            for (int tn=0; tn<4; tn++){
                uint32_t o = b_lane_off + (uint32_t)tn*8*(PITCH*2) + (uint32_t)kk*2;
                ldsm_x2(bhi[tn], base + ST_BHI + o);
                ldsm_x2(blo[tn], base + ST_BLO + o);
            }
            #pragma unroll
            for (int tm=0; tm<4; tm++)
                #pragma unroll
                for (int tn=0; tn<4; tn++){
                    mma_bf16(acc[tm][tn], ahi[tm], bhi[tn]);
                    mma_bf16(acc[tm][tn], ahi[tm], blo[tn]);
                    mma_bf16(acc[tm][tn], alo[tm], bhi[tn]);
                }
        }
    };

    // prologue
    load_regs(0);
    store_stage(0);
    __syncthreads();

    for (int kc=0; kc<NK; kc++){
        if (kc+1 < NK) load_regs(kc+1);
        compute_stage(kc & 1);
        if (kc+1 < NK) store_stage((kc+1) & 1);
        __syncthreads();
    }

    // epilogue: thread (t) in warp holds C rows (t/4, t/4+8), cols (t%4)*2..+1
    const int er = lane >> 2;
    const int ec = (lane & 3) * 2;
    #pragma unroll
    for (int tm=0; tm<4; tm++){
        #pragma unroll
        for (int tn=0; tn<4; tn++){
            int m0 = bm + warp_m + tm*16 + er;
            int n0 = bn + warp_n + tn*8 + ec;
            float* cr = acc[tm][tn];
            #pragma unroll
            for (int h=0; h<2; h++){
                int m = m0 + h*8;
                size_t idx = (size_t)m*N + n0;
                float v0 = cr[h*2+0], v1 = cr[h*2+1];
                if (EPI==1){ v0 = geluf_(v0 + bias[n0]); v1 = geluf_(v1 + bias[n0+1]); }
                else if (EPI==2){ v0 += R1[idx]; v1 += R1[idx+1]; }
                else if (EPI==3){ v0 += bias[n0] + R1[idx]; v1 += bias[n0+1] + R1[idx+1]; }
                float2 o; o.x=v0; o.y=v1;
                *(float2*)&C[idx] = o;
            }
        }
    }
}

// ---------------- layernorm (optionally fused * sigmoid(res)) ----------------
__device__ __forceinline__ float block_reduce_sum(float v, float* red){
    int tid = threadIdx.x;
    #pragma unroll
    for (int o=16;o;o>>=1) v += __shfl_xor_sync(0xffffffffu, v, o);
    if ((tid&31)==0) red[tid>>5] = v;
    __syncthreads();
    if (tid==0){
        float s = 0.f;
        #pragma unroll
        for (int i=0;i<8;i++) s += red[i];
        red[0] = s;
    }
    __syncthreads();
    float r = red[0];
    __syncthreads();
    return r;
}

template<int COLS, int MODE>
__global__ void __launch_bounds__(256) layernorm_k(
    const float* __restrict__ in, const float* __restrict__ gg,
    const float* __restrict__ bb, float* __restrict__ out,
    const float* __restrict__ res, int resLd, int resOff)
{
    constexpr int VPT = COLS/256;
    __shared__ float red[8];
    int row = blockIdx.x;
    const float* x = in + (size_t)row*COLS;
    float v[VPT];
    float s = 0.f;
    #pragma unroll
    for (int i=0;i<VPT;i++){ v[i] = x[i*256 + threadIdx.x]; s += v[i]; }
    s = block_reduce_sum(s, red);
    float mu = s * (1.f/COLS);
    float q = 0.f;
    #pragma unroll
    for (int i=0;i<VPT;i++){ float c = v[i]-mu; q += c*c; }
    q = block_reduce_sum(q, red);
    float rstd = rsqrtf(q*(1.f/COLS) + 1e-5f);
    #pragma unroll
    for (int i=0;i<VPT;i++){
        int c = i*256 + threadIdx.x;
        float o = (v[i]-mu)*rstd*gg[c] + bb[c];
        if (MODE==1){
            float r = res[(size_t)row*resLd + resOff + c];
            o *= sigmoidf_(r);
        }
        out[(size_t)row*COLS + c] = o;
    }
}

// ---------------- depthwise causal conv (K=4) + silu, float4-vectorized ------
template<bool IN_SILU>
__global__ void __launch_bounds__(256) dwconv4_k(
    const float* __restrict__ in, int ld,
    const float* __restrict__ w, const float* __restrict__ bias,
    float* __restrict__ out)
{
    const int ND4 = DI/4;   // 512
    int idx = blockIdx.x*256 + threadIdx.x;
    if (idx >= TOK*ND4) return;
    int d4 = idx & (ND4-1);
    int t  = idx >> 9;                // token index b*SEQ+s
    int s  = t & (SEQ-1);
    int d  = d4*4;
    float wf[16];
    *(float4*)&wf[0]  = *(const float4*)(w + (size_t)(d+0)*4);
    *(float4*)&wf[4]  = *(const float4*)(w + (size_t)(d+1)*4);
    *(float4*)&wf[8]  = *(const float4*)(w + (size_t)(d+2)*4);
    *(float4*)&wf[12] = *(const float4*)(w + (size_t)(d+3)*4);
    float4 acc4 = *(const float4*)(bias + d);
    float* accf = (float*)&acc4;
    #pragma unroll
    for (int k=0;k<Kc;k++){
        int tt = s - (Kc-1) + k;
        if (tt >= 0){
            float4 xv = *(const float4*)(in + (size_t)(t-(Kc-1)+k)*ld + d);
            float* xf = (float*)&xv;
            #pragma unroll
            for (int j=0;j<4;j++){
                float xvv = xf[j];
                if (IN_SILU) xvv = siluf_(xvv);
                accf[j] = fmaf(xvv, wf[j*4+k], accf[j]);
            }
        }
    }
    float4 o;
    o.x = siluf_(accf[0]); o.y = siluf_(accf[1]);
    o.z = siluf_(accf[2]); o.w = siluf_(accf[3]);
    *(float4*)(out + (size_t)t*DI + d) = o;
}

// ---------------- x_proj: proj[t, j] = sum_k xi[t,k] * W[j,k]  (J=33) ---------
__global__ void __launch_bounds__(256) xproj_k(
    const float* __restrict__ xi, const float* __restrict__ W,
    float* __restrict__ proj)
{
    __shared__ float sA[DI];
    int tok = blockIdx.x;
    const float* a = xi + (size_t)tok*DI;
    for (int i=threadIdx.x; i<DI; i+=256) sA[i] = a[i];
    __syncthreads();
    int w = threadIdx.x >> 5, lane = threadIdx.x & 31;
    for (int j = w; j < 33; j += 8){
        const float* Bw = W + (size_t)j*DI;
        float s = 0.f;
        for (int k = lane; k < DI; k += 32) s = fmaf(sA[k], Bw[k], s);
        #pragma unroll
        for (int o=16;o;o>>=1) s += __shfl_xor_sync(0xffffffffu, s, o);
        if (lane==0) proj[(size_t)tok*33 + j] = s;
    }
}

// ---------------- selective scan ---------------------------------------------
#define TCH 64
__global__ void __launch_bounds__(128) scan_k(
    const float* __restrict__ proj, const float* __restrict__ xi,
    const float* __restrict__ dtw, const float* __restrict__ dtb,
    const float* __restrict__ Dp, float* __restrict__ y)
{
    int b = blockIdx.y;
    int d = blockIdx.x*128 + threadIdx.x;
    float w_dt = dtw[d];
    float b_dt = dtb[d];
    float Dd   = Dp[d];
    float h[Nst];
    #pragma unroll
    for (int n=0;n<Nst;n++) h[n]=0.f;

    __shared__ float sp[TCH][36];
    const float* projB = proj + (size_t)b*SEQ*33;
    const float* xiB   = xi   + (size_t)b*SEQ*DI + d;
    float*       yB    = y    + (size_t)b*SEQ*DI + d;

    for (int t0=0; t0<SEQ; t0+=TCH){
        __syncthreads();
        for (int i=threadIdx.x; i<TCH*33; i+=128){
            int t = i/33, j = i%33;
            int slot = (j==0) ? 0 : (j+3);
            sp[t][slot] = projB[(size_t)(t0)*33 + i];
        }
        __syncthreads();
        for (int tt=0; tt<TCH; tt++){
            int t = t0+tt;
            const float* r = sp[tt];
            float z = fmaf(r[0], w_dt, b_dt);
            float dt = (z > 15.f) ? z : log1pf(__expf(z));
            float xv = xiB[(size_t)t*DI];
            float4 B0 = *(const float4*)&r[4];
            float4 B1 = *(const float4*)&r[8];
            float4 B2 = *(const float4*)&r[12];
            float4 B3 = *(const float4*)&r[16];
            float4 C0 = *(const float4*)&r[20];
            float4 C1 = *(const float4*)&r[24];
            float4 C2 = *(const float4*)&r[28];
            float4 C3 = *(const float4*)&r[32];
            float bArr[16] = {B0.x,B0.y,B0.z,B0.w,B1.x,B1.y,B1.z,B1.w,
                              B2.x,B2.y,B2.z,B2.w,B3.x,B3.y,B3.z,B3.w};
            float cArr[16] = {C0.x,C0.y,C0.z,C0.w,C1.x,C1.y,C1.z,C1.w,
                              C2.x,C2.y,C2.z,C2.w,C3.x,C3.y,C3.z,C3.w};
            float yv = 0.f;
            #pragma unroll
            for (int n=0;n<Nst;n++){
                float An = -(float)(n+1);
                float u = fmaf(h[n], An, xv * bArr[n]);
                h[n] = fmaf(dt, u, h[n]);
                yv = fmaf(h[n], cArr[n], yv);
            }
            yB[(size_t)t*DI] = fmaf(xv, Dd, yv);
        }
    }
}

// ---------------- host side ---------------------------------------------------
static float* sym_addr(const void* symbol){
    void* p = nullptr;
    cudaGetSymbolAddress(&p, symbol);
    return (float*)p;
}

template<int EPI>
static void launch_gemm(const float* A, const float* B, float* C,
                        int M, int N, int K, const float* bias, const float* R1){
    static bool attr_set = false;
    cudaFuncSetAttribute(mma_gemm_nt<EPI>, cudaFuncAttributeMaxDynamicSharedMemorySize,
                         GEMM_SMEM);
    (void)attr_set;
    dim3 grid(N/BN, M/BM);
    mma_gemm_nt<EPI><<<grid, 256, GEMM_SMEM>>>(A, B, C, M, N, K, bias, R1);
}

extern "C" void kernel_launch(void* const* d_in, const int* in_sizes, int n_in,
                              void* d_out, int out_size)
{
    const float* hidden   = (const float*)d_in[0];
    const float* in_ng    = (const float*)d_in[1];
    const float* in_nb    = (const float*)d_in[2];
    const float* ln_g     = (const float*)d_in[3];
    const float* ln_b     = (const float*)d_in[4];
    const float* in_proj  = (const float*)d_in[5];   // (L, 2*DI, H)
    const float* conv_w   = (const float*)d_in[6];   // (L, 2, DI, K)
    const float* conv_b   = (const float*)d_in[7];   // (L, 2, DI)
    const float* x_proj   = (const float*)d_in[8];   // (L, 33, DI)
    const float* dt_w     = (const float*)d_in[9];   // (L, DI, 1)
    const float* dt_b     = (const float*)d_in[10];  // (L, DI)
    const float* Dparam   = (const float*)d_in[11];  // (L, DI)
    const float* mln_g    = (const float*)d_in[12];
    const float* mln_b    = (const float*)d_in[13];
    const float* out_proj = (const float*)d_in[14];  // (L, H, DI)
    const float* op1_w    = (const float*)d_in[15];
    const float* op1_b    = (const float*)d_in[16];
    const float* op2_w    = (const float*)d_in[17];
    const float* op2_b    = (const float*)d_in[18];
    float* out = (float*)d_out;

    float* x   = sym_addr(g_x);
    float* xn  = sym_addr(g_xn);
    float* xr  = sym_addr(g_xr);
    float* c1  = sym_addr(g_c1);
    float* xi  = sym_addr(g_xi);
    float* pj  = sym_addr(g_proj);
    float* yb  = sym_addr(g_y);
    float* y2  = sym_addr(g_y2);
    float* t1  = sym_addr(g_t1);

    // x = LN(hidden)
    layernorm_k<Hd,0><<<TOK,256>>>(hidden, in_ng, in_nb, x, nullptr, 0, 0);

    for (int l=0; l<Ld; l++){
        // xn = LN_l(x)
        layernorm_k<Hd,0><<<TOK,256>>>(x, ln_g + l*Hd, ln_b + l*Hd, xn, nullptr, 0, 0);
        // xr = xn @ in_proj_w[l]^T   (TOK x 4096)
        launch_gemm<0>(xn, in_proj + (size_t)l*2*DI*Hd, xr, TOK, 2*DI, Hd, nullptr, nullptr);
        // conv1: input = silu(xr[:, :DI]) (ld 4096) -> c1 ; conv2 -> xi
        {
            int blocks = (TOK*(DI/4) + 255)/256;
            dwconv4_k<true><<<blocks,256>>>(
                xr, 2*DI,
                conv_w + (size_t)(l*2+0)*DI*Kc, conv_b + (size_t)(l*2+0)*DI, c1);
            dwconv4_k<false><<<blocks,256>>>(
                c1, DI,
                conv_w + (size_t)(l*2+1)*DI*Kc, conv_b + (size_t)(l*2+1)*DI, xi);
        }
        // proj = xi @ x_proj_w[l]^T  (TOK x 33)
        xproj_k<<<TOK,256>>>(xi, x_proj + (size_t)l*33*DI, pj);
        // scan -> y (+ xi * D fused)
        {
            dim3 grid(DI/128, BATCH);
            scan_k<<<grid,128>>>(pj, xi, dt_w + (size_t)l*DI, dt_b + (size_t)l*DI,
                                 Dparam + (size_t)l*DI, yb);
        }
        // y2 = LN_mamba(y) * sigmoid(res)
        layernorm_k<DI,1><<<TOK,256>>>(yb, mln_g + (size_t)l*DI, mln_b + (size_t)l*DI,
                                       y2, xr, 2*DI, DI);
        // x = x + y2 @ out_proj_w[l]^T
        launch_gemm<2>(y2, out_proj + (size_t)l*Hd*DI, x, TOK, Hd, DI, nullptr, x);
    }

    // MLP
    launch_gemm<1>(x, op1_w, t1, TOK, Hd, Hd, op1_b, nullptr);
    launch_gemm<3>(t1, op2_w, out, TOK, Hd, Hd, op2_b, hidden);
}